// round 1
// baseline (speedup 1.0000x reference)
#include <cuda_runtime.h>
#include <mma.h>
#include <math.h>

using namespace nvcuda;

// Problem constants
#define T_TOK 2048
#define HID   2880
#define INTERN 2880
#define NE    8
#define TOPK  4
#define N1    (2*INTERN)          // 5760
#define PAD_ROWS (NE*T_TOK)       // 16384 (padded per-expert row space)

#define ALPHA 1.702f
#define LIMITV 7.0f

// ---------------- scratch (static device memory; no allocs allowed) ----------
__device__ int   d_counts[NE];
__device__ int   d_rtok[NE * T_TOK];          // per-expert gathered token ids
__device__ int   d_pos [T_TOK * TOPK];        // token-slot -> local row in expert list
__device__ int   d_topidx[T_TOK * TOPK];
__device__ float d_topw [T_TOK * TOPK];
__device__ float d_h  [(size_t)PAD_ROWS * N1];     // gate+up pre-activation (377 MB)
__device__ float d_act[(size_t)PAD_ROWS * INTERN]; // swiglu output (188 MB)
__device__ float d_y2 [(size_t)PAD_ROWS * HID];    // raw down-proj (no bias/weight) (188 MB)

// ---------------- router: fp32-exact logits + top4 + softmax -----------------
__global__ void router_kernel(const float* __restrict__ x,
                              const float* __restrict__ gw,
                              const float* __restrict__ gb) {
    int t = blockIdx.x;
    float acc[NE];
    #pragma unroll
    for (int e = 0; e < NE; e++) acc[e] = 0.f;

    for (int h = threadIdx.x; h < HID; h += blockDim.x) {
        float xv = x[(size_t)t * HID + h];
        const float* g = gw + (size_t)h * NE;
        #pragma unroll
        for (int e = 0; e < NE; e++) acc[e] += xv * g[e];
    }
    // warp reduce
    #pragma unroll
    for (int off = 16; off > 0; off >>= 1) {
        #pragma unroll
        for (int e = 0; e < NE; e++)
            acc[e] += __shfl_down_sync(0xffffffffu, acc[e], off);
    }
    __shared__ float sred[4][NE];
    int w = threadIdx.x >> 5, lane = threadIdx.x & 31;
    if (lane == 0) {
        #pragma unroll
        for (int e = 0; e < NE; e++) sred[w][e] = acc[e];
    }
    __syncthreads();
    if (threadIdx.x == 0) {
        float lg[NE];
        #pragma unroll
        for (int e = 0; e < NE; e++)
            lg[e] = sred[0][e] + sred[1][e] + sred[2][e] + sred[3][e] + gb[e];
        int   idx[TOPK];
        float val[TOPK];
        bool used[NE];
        #pragma unroll
        for (int e = 0; e < NE; e++) used[e] = false;
        #pragma unroll
        for (int k = 0; k < TOPK; k++) {
            int best = -1; float bv = -INFINITY;
            #pragma unroll
            for (int e = 0; e < NE; e++)
                if (!used[e] && lg[e] > bv) { bv = lg[e]; best = e; }
            used[best] = true; idx[k] = best; val[k] = bv;
        }
        float m = val[0];
        float ex[TOPK]; float s = 0.f;
        #pragma unroll
        for (int k = 0; k < TOPK; k++) { ex[k] = expf(val[k] - m); s += ex[k]; }
        float inv = 1.f / s;
        #pragma unroll
        for (int k = 0; k < TOPK; k++) {
            d_topidx[t * TOPK + k] = idx[k];
            d_topw [t * TOPK + k] = ex[k] * inv;
        }
    }
}

__global__ void reset_kernel() {
    if (threadIdx.x < NE) d_counts[threadIdx.x] = 0;
}

// atomic order only picks storage slots; values are per-(t,k), so the final
// output is bitwise deterministic regardless of ordering.
__global__ void build_kernel() {
    int t = blockIdx.x * blockDim.x + threadIdx.x;
    if (t >= T_TOK) return;
    #pragma unroll
    for (int k = 0; k < TOPK; k++) {
        int e = d_topidx[t * TOPK + k];
        int p = atomicAdd(&d_counts[e], 1);
        d_rtok[e * T_TOK + p] = t;
        d_pos[t * TOPK + k] = p;
    }
}

// ---------------- wmma tf32 GEMM tiles -----------------
#define BM 64
#define BN 64
#define BK 32
#define APAD 8
#define BPAD 8

// GEMM1: h[e*T + r, :] = x[rtok[e][r], :] @ w1[e]   (N = 5760, K = 2880)
__global__ void gemm1_kernel(const float* __restrict__ x,
                             const float* __restrict__ w1) {
    int e  = blockIdx.z;
    int m0 = blockIdx.y * BM;
    int n0 = blockIdx.x * BN;
    int cnt = d_counts[e];
    if (m0 >= cnt) return;

    __shared__ float As[BM][BK + APAD];
    __shared__ float Bs[BK][BN + BPAD];
    __shared__ int   stok[BM];

    int tid = threadIdx.x;
    if (tid < BM) {
        int r = m0 + tid;
        stok[tid] = (r < cnt) ? d_rtok[e * T_TOK + r] : d_rtok[e * T_TOK];
    }
    __syncthreads();

    const float* Bbase = w1 + (size_t)e * HID * N1 + n0;

    wmma::fragment<wmma::accumulator, 16, 16, 8, float> acc[2][2];
    #pragma unroll
    for (int i = 0; i < 2; i++)
        #pragma unroll
        for (int j = 0; j < 2; j++) wmma::fill_fragment(acc[i][j], 0.f);

    int wid = tid >> 5;
    int wm = wid >> 1, wn = wid & 1;

    for (int k0 = 0; k0 < HID; k0 += BK) {
        // load A tile (gathered rows), convert to tf32
        #pragma unroll
        for (int i = tid; i < BM * (BK / 4); i += 128) {
            int r = i >> 3; int c = (i & 7) * 4;
            const float4 v = *(const float4*)(x + (size_t)stok[r] * HID + k0 + c);
            As[r][c + 0] = wmma::__float_to_tf32(v.x);
            As[r][c + 1] = wmma::__float_to_tf32(v.y);
            As[r][c + 2] = wmma::__float_to_tf32(v.z);
            As[r][c + 3] = wmma::__float_to_tf32(v.w);
        }
        // load B tile
        #pragma unroll
        for (int i = tid; i < BK * (BN / 4); i += 128) {
            int r = i >> 4; int c = (i & 15) * 4;
            const float4 v = *(const float4*)(Bbase + (size_t)(k0 + r) * N1 + c);
            Bs[r][c + 0] = wmma::__float_to_tf32(v.x);
            Bs[r][c + 1] = wmma::__float_to_tf32(v.y);
            Bs[r][c + 2] = wmma::__float_to_tf32(v.z);
            Bs[r][c + 3] = wmma::__float_to_tf32(v.w);
        }
        __syncthreads();

        #pragma unroll
        for (int kk = 0; kk < BK; kk += 8) {
            wmma::fragment<wmma::matrix_a, 16, 16, 8, wmma::precision::tf32, wmma::row_major> af[2];
            wmma::fragment<wmma::matrix_b, 16, 16, 8, wmma::precision::tf32, wmma::row_major> bf[2];
            #pragma unroll
            for (int i = 0; i < 2; i++)
                wmma::load_matrix_sync(af[i], &As[wm * 32 + i * 16][kk], BK + APAD);
            #pragma unroll
            for (int j = 0; j < 2; j++)
                wmma::load_matrix_sync(bf[j], &Bs[kk][wn * 32 + j * 16], BN + BPAD);
            #pragma unroll
            for (int i = 0; i < 2; i++)
                #pragma unroll
                for (int j = 0; j < 2; j++)
                    wmma::mma_sync(acc[i][j], af[i], bf[j], acc[i][j]);
        }
        __syncthreads();
    }

    float* Cbase = d_h + (size_t)(e * T_TOK + m0) * N1 + n0;
    #pragma unroll
    for (int i = 0; i < 2; i++)
        #pragma unroll
        for (int j = 0; j < 2; j++)
            wmma::store_matrix_sync(Cbase + (size_t)(wm * 32 + i * 16) * N1 + wn * 32 + j * 16,
                                    acc[i][j], N1, wmma::mem_row_major);
}

// ---------------- clamped SwiGLU ----------------
__global__ void act_kernel(const float* __restrict__ b1) {
    int row = blockIdx.x;
    int e = row / T_TOK;
    int r = row - e * T_TOK;
    if (r >= d_counts[e]) return;
    const float* hrow = d_h + (size_t)row * N1;
    const float* be   = b1 + (size_t)e * N1;
    float* arow = d_act + (size_t)row * INTERN;
    for (int i = threadIdx.x; i < INTERN; i += blockDim.x) {
        float g = hrow[i] + be[i];
        float l = hrow[INTERN + i] + be[INTERN + i];
        g = fminf(g, LIMITV);
        l = fminf(fmaxf(l, -LIMITV), LIMITV);
        float s = 1.0f / (1.0f + expf(-ALPHA * g));
        arow[i] = g * s * (l + 1.0f);
    }
}

// GEMM2: y2[e*T + r, :] = act[e*T + r, :] @ w2[e]   (N = 2880, K = 2880)
__global__ void gemm2_kernel(const float* __restrict__ w2) {
    int e  = blockIdx.z;
    int m0 = blockIdx.y * BM;
    int n0 = blockIdx.x * BN;
    int cnt = d_counts[e];
    if (m0 >= cnt) return;

    __shared__ float As[BM][BK + APAD];
    __shared__ float Bs[BK][BN + BPAD];

    int tid = threadIdx.x;
    const float* Abase = d_act + (size_t)(e * T_TOK + m0) * INTERN;
    const float* Bbase = w2 + (size_t)e * INTERN * HID + n0;

    wmma::fragment<wmma::accumulator, 16, 16, 8, float> acc[2][2];
    #pragma unroll
    for (int i = 0; i < 2; i++)
        #pragma unroll
        for (int j = 0; j < 2; j++) wmma::fill_fragment(acc[i][j], 0.f);

    int wid = tid >> 5;
    int wm = wid >> 1, wn = wid & 1;

    for (int k0 = 0; k0 < INTERN; k0 += BK) {
        #pragma unroll
        for (int i = tid; i < BM * (BK / 4); i += 128) {
            int r = i >> 3; int c = (i & 7) * 4;
            const float4 v = *(const float4*)(Abase + (size_t)r * INTERN + k0 + c);
            As[r][c + 0] = wmma::__float_to_tf32(v.x);
            As[r][c + 1] = wmma::__float_to_tf32(v.y);
            As[r][c + 2] = wmma::__float_to_tf32(v.z);
            As[r][c + 3] = wmma::__float_to_tf32(v.w);
        }
        #pragma unroll
        for (int i = tid; i < BK * (BN / 4); i += 128) {
            int r = i >> 4; int c = (i & 15) * 4;
            const float4 v = *(const float4*)(Bbase + (size_t)(k0 + r) * HID + c);
            Bs[r][c + 0] = wmma::__float_to_tf32(v.x);
            Bs[r][c + 1] = wmma::__float_to_tf32(v.y);
            Bs[r][c + 2] = wmma::__float_to_tf32(v.z);
            Bs[r][c + 3] = wmma::__float_to_tf32(v.w);
        }
        __syncthreads();

        #pragma unroll
        for (int kk = 0; kk < BK; kk += 8) {
            wmma::fragment<wmma::matrix_a, 16, 16, 8, wmma::precision::tf32, wmma::row_major> af[2];
            wmma::fragment<wmma::matrix_b, 16, 16, 8, wmma::precision::tf32, wmma::row_major> bf[2];
            #pragma unroll
            for (int i = 0; i < 2; i++)
                wmma::load_matrix_sync(af[i], &As[wm * 32 + i * 16][kk], BK + APAD);
            #pragma unroll
            for (int j = 0; j < 2; j++)
                wmma::load_matrix_sync(bf[j], &Bs[kk][wn * 32 + j * 16], BN + BPAD);
            #pragma unroll
            for (int i = 0; i < 2; i++)
                #pragma unroll
                for (int j = 0; j < 2; j++)
                    wmma::mma_sync(acc[i][j], af[i], bf[j], acc[i][j]);
        }
        __syncthreads();
    }

    float* Cbase = d_y2 + (size_t)(e * T_TOK + m0) * HID + n0;
    #pragma unroll
    for (int i = 0; i < 2; i++)
        #pragma unroll
        for (int j = 0; j < 2; j++)
            wmma::store_matrix_sync(Cbase + (size_t)(wm * 32 + i * 16) * HID + wn * 32 + j * 16,
                                    acc[i][j], HID, wmma::mem_row_major);
}

// ---------------- deterministic combine (bias + routing weight here) ---------
__global__ void combine_kernel(const float* __restrict__ b2,
                               float* __restrict__ y) {
    int t = blockIdx.x;
    __shared__ int   se[TOPK];
    __shared__ int   sp[TOPK];
    __shared__ float sw[TOPK];
    if (threadIdx.x < TOPK) {
        se[threadIdx.x] = d_topidx[t * TOPK + threadIdx.x];
        sp[threadIdx.x] = d_pos  [t * TOPK + threadIdx.x];
        sw[threadIdx.x] = d_topw [t * TOPK + threadIdx.x];
    }
    __syncthreads();
    for (int n = threadIdx.x; n < HID; n += blockDim.x) {
        float s = 0.f;
        #pragma unroll
        for (int k = 0; k < TOPK; k++) {
            int e = se[k];
            size_t row = (size_t)(e * T_TOK + sp[k]);
            s += sw[k] * (d_y2[row * HID + n] + b2[(size_t)e * HID + n]);
        }
        y[(size_t)t * HID + n] = s;
    }
}

// ---------------- launch ----------------
extern "C" void kernel_launch(void* const* d_in, const int* in_sizes, int n_in,
                              void* d_out, int out_size) {
    const float* x   = (const float*)d_in[0];
    const float* gw  = (const float*)d_in[1];
    const float* gb  = (const float*)d_in[2];
    const float* w1  = (const float*)d_in[3];
    const float* b1  = (const float*)d_in[4];
    const float* w2  = (const float*)d_in[5];
    const float* b2  = (const float*)d_in[6];
    float* y = (float*)d_out;

    reset_kernel<<<1, 32>>>();
    router_kernel<<<T_TOK, 128>>>(x, gw, gb);
    build_kernel<<<(T_TOK + 255) / 256, 256>>>();

    dim3 g1(N1 / BN, T_TOK / BM, NE);   // (90, 32, 8)
    gemm1_kernel<<<g1, 128>>>(x, w1);

    act_kernel<<<PAD_ROWS, 256>>>(b1);

    dim3 g2(HID / BN, T_TOK / BM, NE);  // (45, 32, 8)
    gemm2_kernel<<<g2, 128>>>(w2);

    combine_kernel<<<T_TOK, 256>>>(b2, y);
}

// round 3
// speedup vs baseline: 1.5226x; 1.5226x over previous
#include <cuda_runtime.h>
#include <mma.h>
#include <math.h>
#include <cstdint>

using namespace nvcuda;

#define T_TOK 2048
#define HID   2880
#define INTERN 2880
#define NE    8
#define TOPK  4
#define N1    (2*INTERN)          // 5760
#define ALPHA 1.702f
#define LIMITV 7.0f

// GEMM tiling
#define BM 128
#define BN 64
#define BK 16
#define LDA 24                    // BK + 8 pad (96B rows, 16B aligned)
#define LDB 72                    // BN + 8 pad (288B rows, 16B aligned)
#define KT1 (HID/BK)              // 180
#define KT2 (INTERN/BK)           // 180

// ---------------- scratch ----------------
__device__ int   d_counts[NE];
__device__ int   d_rtok[NE * T_TOK];
__device__ int   d_pos [T_TOK * TOPK];
__device__ int   d_topidx[T_TOK * TOPK];
__device__ float d_topw [T_TOK * TOPK];
__device__ float d_act[(size_t)NE * T_TOK * INTERN]; // 188 MB
__device__ float d_y2 [(size_t)NE * T_TOK * HID];    // 188 MB

__device__ __forceinline__ void cpa16(float* smem, const float* gmem) {
    uint32_t s = (uint32_t)__cvta_generic_to_shared(smem);
    asm volatile("cp.async.cg.shared.global [%0], [%1], 16;\n" :: "r"(s), "l"(gmem));
}
#define CP_COMMIT() asm volatile("cp.async.commit_group;\n")
#define CP_WAIT1()  asm volatile("cp.async.wait_group 1;\n")

// ---------------- router (fp32 exact) ----------------
__global__ void router_kernel(const float* __restrict__ x,
                              const float* __restrict__ gw,
                              const float* __restrict__ gb) {
    int t = blockIdx.x;
    float acc[NE];
    #pragma unroll
    for (int e = 0; e < NE; e++) acc[e] = 0.f;
    for (int h = threadIdx.x; h < HID; h += blockDim.x) {
        float xv = x[(size_t)t * HID + h];
        const float* g = gw + (size_t)h * NE;
        #pragma unroll
        for (int e = 0; e < NE; e++) acc[e] += xv * g[e];
    }
    #pragma unroll
    for (int off = 16; off > 0; off >>= 1)
        #pragma unroll
        for (int e = 0; e < NE; e++)
            acc[e] += __shfl_down_sync(0xffffffffu, acc[e], off);
    __shared__ float sred[4][NE];
    int w = threadIdx.x >> 5, lane = threadIdx.x & 31;
    if (lane == 0)
        #pragma unroll
        for (int e = 0; e < NE; e++) sred[w][e] = acc[e];
    __syncthreads();
    if (threadIdx.x == 0) {
        float lg[NE];
        #pragma unroll
        for (int e = 0; e < NE; e++)
            lg[e] = sred[0][e] + sred[1][e] + sred[2][e] + sred[3][e] + gb[e];
        int idx[TOPK]; float val[TOPK]; bool used[NE];
        #pragma unroll
        for (int e = 0; e < NE; e++) used[e] = false;
        #pragma unroll
        for (int k = 0; k < TOPK; k++) {
            int best = -1; float bv = -INFINITY;
            #pragma unroll
            for (int e = 0; e < NE; e++)
                if (!used[e] && lg[e] > bv) { bv = lg[e]; best = e; }
            used[best] = true; idx[k] = best; val[k] = bv;
        }
        float m = val[0], ex[TOPK], s = 0.f;
        #pragma unroll
        for (int k = 0; k < TOPK; k++) { ex[k] = expf(val[k] - m); s += ex[k]; }
        float inv = 1.f / s;
        #pragma unroll
        for (int k = 0; k < TOPK; k++) {
            d_topidx[t * TOPK + k] = idx[k];
            d_topw [t * TOPK + k] = ex[k] * inv;
        }
    }
}

__global__ void reset_kernel() { if (threadIdx.x < NE) d_counts[threadIdx.x] = 0; }

__global__ void build_kernel() {
    int t = blockIdx.x * blockDim.x + threadIdx.x;
    if (t >= T_TOK) return;
    #pragma unroll
    for (int k = 0; k < TOPK; k++) {
        int e = d_topidx[t * TOPK + k];
        int p = atomicAdd(&d_counts[e], 1);
        d_rtok[e * T_TOK + p] = t;
        d_pos[t * TOPK + k] = p;
    }
}

// ---------------- GEMM1 fused with clamped SwiGLU ----------------
__global__ __launch_bounds__(256) void gemm1_kernel(const float* __restrict__ x,
                                                    const float* __restrict__ w1,
                                                    const float* __restrict__ b1) {
    int e  = blockIdx.z;
    int m0 = blockIdx.y * BM;
    int n0 = blockIdx.x * BN;
    int cnt = d_counts[e];
    if (m0 >= cnt) return;

    __shared__ float sbuf[2*BM*LDA + 2*2*BK*LDB];   // 10752 floats = 43KB
    __shared__ int   stok[BM];
    float* As = sbuf;                   // 2 stages of [BM][LDA]
    float* Bg = sbuf + 2*BM*LDA;        // 2 stages of [BK][LDB]
    float* Bl = Bg   + 2*BK*LDB;

    int tid = threadIdx.x;
    if (tid < BM) {
        int r = m0 + tid;
        stok[tid] = (r < cnt) ? d_rtok[e * T_TOK + r] : d_rtok[e * T_TOK];
    }
    __syncthreads();

    const float* Bbase_g = w1 + (size_t)e * HID * N1 + n0;
    const float* Bbase_l = Bbase_g + INTERN;

    auto load_stage = [&](int s, int k0) {
        float* as = As + s * BM * LDA;
        #pragma unroll
        for (int j = 0; j < 2; j++) {
            int idx = tid + j * 256;
            int r = idx >> 2, c = (idx & 3) << 2;
            cpa16(as + r * LDA + c, x + (size_t)stok[r] * HID + k0 + c);
        }
        float* bg = Bg + s * BK * LDB;
        float* bl = Bl + s * BK * LDB;
        int r = tid >> 4, c = (tid & 15) << 2;
        cpa16(bg + r * LDB + c, Bbase_g + (size_t)(k0 + r) * N1 + c);
        cpa16(bl + r * LDB + c, Bbase_l + (size_t)(k0 + r) * N1 + c);
    };

    wmma::fragment<wmma::accumulator, 16, 16, 8, float> ag[2][2], al[2][2];
    #pragma unroll
    for (int i = 0; i < 2; i++)
        #pragma unroll
        for (int j = 0; j < 2; j++) { wmma::fill_fragment(ag[i][j], 0.f); wmma::fill_fragment(al[i][j], 0.f); }

    int wid = tid >> 5, wm = wid >> 1, wn = wid & 1;   // 8 warps: 4m x 2n, warp tile 32x32

    load_stage(0, 0);
    CP_COMMIT();

    for (int kt = 0; kt < KT1; kt++) {
        if (kt + 1 < KT1) load_stage((kt + 1) & 1, (kt + 1) * BK);
        CP_COMMIT();
        CP_WAIT1();
        __syncthreads();
        float* as = As + (kt & 1) * BM * LDA;
        float* bg = Bg + (kt & 1) * BK * LDB;
        float* bl = Bl + (kt & 1) * BK * LDB;
        #pragma unroll
        for (int kk = 0; kk < BK; kk += 8) {
            wmma::fragment<wmma::matrix_a, 16, 16, 8, wmma::precision::tf32, wmma::row_major> af[2];
            wmma::fragment<wmma::matrix_b, 16, 16, 8, wmma::precision::tf32, wmma::row_major> bfg[2], bfl[2];
            #pragma unroll
            for (int i = 0; i < 2; i++) {
                wmma::load_matrix_sync(af[i], as + (wm * 32 + i * 16) * LDA + kk, LDA);
                #pragma unroll
                for (int t = 0; t < af[i].num_elements; t++)
                    af[i].x[t] = wmma::__float_to_tf32(af[i].x[t]);
            }
            #pragma unroll
            for (int j = 0; j < 2; j++) {
                wmma::load_matrix_sync(bfg[j], bg + kk * LDB + wn * 32 + j * 16, LDB);
                wmma::load_matrix_sync(bfl[j], bl + kk * LDB + wn * 32 + j * 16, LDB);
                #pragma unroll
                for (int t = 0; t < bfg[j].num_elements; t++) {
                    bfg[j].x[t] = wmma::__float_to_tf32(bfg[j].x[t]);
                    bfl[j].x[t] = wmma::__float_to_tf32(bfl[j].x[t]);
                }
            }
            #pragma unroll
            for (int i = 0; i < 2; i++)
                #pragma unroll
                for (int j = 0; j < 2; j++) {
                    wmma::mma_sync(ag[i][j], af[i], bfg[j], ag[i][j]);
                    wmma::mma_sync(al[i][j], af[i], bfl[j], al[i][j]);
                }
        }
        __syncthreads();
    }

    // ---- fused epilogue: stage gate, stage lin, apply clamped SwiGLU ----
    float* stg = sbuf;   // reuse pipeline smem: 128*72 floats fits in 10752
    #pragma unroll
    for (int i = 0; i < 2; i++)
        #pragma unroll
        for (int j = 0; j < 2; j++)
            wmma::store_matrix_sync(stg + (size_t)(wm * 32 + i * 16) * LDB + wn * 32 + j * 16,
                                    ag[i][j], LDB, wmma::mem_row_major);
    __syncthreads();

    int r  = tid >> 1;
    int cb = (tid & 1) * 32;
    float gv[32];
    #pragma unroll
    for (int q = 0; q < 8; q++) {
        float4 v = *(const float4*)(stg + r * LDB + cb + q * 4);
        gv[q*4+0] = v.x; gv[q*4+1] = v.y; gv[q*4+2] = v.z; gv[q*4+3] = v.w;
    }
    __syncthreads();

    #pragma unroll
    for (int i = 0; i < 2; i++)
        #pragma unroll
        for (int j = 0; j < 2; j++)
            wmma::store_matrix_sync(stg + (size_t)(wm * 32 + i * 16) * LDB + wn * 32 + j * 16,
                                    al[i][j], LDB, wmma::mem_row_major);
    __syncthreads();

    const float* bgp = b1 + (size_t)e * N1 + n0;
    const float* blp = bgp + INTERN;
    float* outp = d_act + (size_t)(e * T_TOK + m0 + r) * INTERN + n0;
    #pragma unroll
    for (int q = 0; q < 8; q++) {
        float4 lv = *(const float4*)(stg + r * LDB + cb + q * 4);
        float lraw[4] = {lv.x, lv.y, lv.z, lv.w};
        float4 o;
        float* op = &o.x;
        #pragma unroll
        for (int w = 0; w < 4; w++) {
            int c = cb + q * 4 + w;
            float g = fminf(gv[q*4+w] + bgp[c], LIMITV);
            float l = fminf(fmaxf(lraw[w] + blp[c], -LIMITV), LIMITV);
            float s = 1.0f / (1.0f + expf(-ALPHA * g));
            op[w] = g * s * (l + 1.0f);
        }
        *(float4*)(outp + cb + q * 4) = o;
    }
}

// ---------------- GEMM2: y2 = act @ w2[e] ----------------
__global__ __launch_bounds__(256) void gemm2_kernel(const float* __restrict__ w2) {
    int e  = blockIdx.z;
    int m0 = blockIdx.y * BM;
    int n0 = blockIdx.x * BN;
    int cnt = d_counts[e];
    if (m0 >= cnt) return;

    __shared__ float sbuf[2*BM*LDA + 2*BK*LDB];   // 8448 floats = 33.8KB
    float* As = sbuf;
    float* Bs = sbuf + 2*BM*LDA;

    int tid = threadIdx.x;
    const float* Abase = d_act + (size_t)(e * T_TOK + m0) * INTERN;
    const float* Bbase = w2 + (size_t)e * INTERN * HID + n0;

    auto load_stage = [&](int s, int k0) {
        float* as = As + s * BM * LDA;
        #pragma unroll
        for (int j = 0; j < 2; j++) {
            int idx = tid + j * 256;
            int r = idx >> 2, c = (idx & 3) << 2;
            cpa16(as + r * LDA + c, Abase + (size_t)r * INTERN + k0 + c);
        }
        float* bs = Bs + s * BK * LDB;
        int r = tid >> 4, c = (tid & 15) << 2;
        cpa16(bs + r * LDB + c, Bbase + (size_t)(k0 + r) * HID + c);
    };

    wmma::fragment<wmma::accumulator, 16, 16, 8, float> acc[2][2];
    #pragma unroll
    for (int i = 0; i < 2; i++)
        #pragma unroll
        for (int j = 0; j < 2; j++) wmma::fill_fragment(acc[i][j], 0.f);

    int wid = tid >> 5, wm = wid >> 1, wn = wid & 1;

    load_stage(0, 0);
    CP_COMMIT();

    for (int kt = 0; kt < KT2; kt++) {
        if (kt + 1 < KT2) load_stage((kt + 1) & 1, (kt + 1) * BK);
        CP_COMMIT();
        CP_WAIT1();
        __syncthreads();
        float* as = As + (kt & 1) * BM * LDA;
        float* bs = Bs + (kt & 1) * BK * LDB;
        #pragma unroll
        for (int kk = 0; kk < BK; kk += 8) {
            wmma::fragment<wmma::matrix_a, 16, 16, 8, wmma::precision::tf32, wmma::row_major> af[2];
            wmma::fragment<wmma::matrix_b, 16, 16, 8, wmma::precision::tf32, wmma::row_major> bf[2];
            #pragma unroll
            for (int i = 0; i < 2; i++) {
                wmma::load_matrix_sync(af[i], as + (wm * 32 + i * 16) * LDA + kk, LDA);
                #pragma unroll
                for (int t = 0; t < af[i].num_elements; t++)
                    af[i].x[t] = wmma::__float_to_tf32(af[i].x[t]);
            }
            #pragma unroll
            for (int j = 0; j < 2; j++) {
                wmma::load_matrix_sync(bf[j], bs + kk * LDB + wn * 32 + j * 16, LDB);
                #pragma unroll
                for (int t = 0; t < bf[j].num_elements; t++)
                    bf[j].x[t] = wmma::__float_to_tf32(bf[j].x[t]);
            }
            #pragma unroll
            for (int i = 0; i < 2; i++)
                #pragma unroll
                for (int j = 0; j < 2; j++)
                    wmma::mma_sync(acc[i][j], af[i], bf[j], acc[i][j]);
        }
        __syncthreads();
    }

    float* Cbase = d_y2 + (size_t)(e * T_TOK + m0) * HID + n0;
    #pragma unroll
    for (int i = 0; i < 2; i++)
        #pragma unroll
        for (int j = 0; j < 2; j++)
            wmma::store_matrix_sync(Cbase + (size_t)(wm * 32 + i * 16) * HID + wn * 32 + j * 16,
                                    acc[i][j], HID, wmma::mem_row_major);
}

// ---------------- deterministic combine ----------------
__global__ void combine_kernel(const float* __restrict__ b2,
                               float* __restrict__ y) {
    int t = blockIdx.x;
    __shared__ int se[TOPK]; __shared__ int sp[TOPK]; __shared__ float sw[TOPK];
    if (threadIdx.x < TOPK) {
        se[threadIdx.x] = d_topidx[t * TOPK + threadIdx.x];
        sp[threadIdx.x] = d_pos  [t * TOPK + threadIdx.x];
        sw[threadIdx.x] = d_topw [t * TOPK + threadIdx.x];
    }
    __syncthreads();
    for (int n = threadIdx.x; n < HID; n += blockDim.x) {
        float s = 0.f;
        #pragma unroll
        for (int k = 0; k < TOPK; k++) {
            int e = se[k];
            size_t row = (size_t)(e * T_TOK + sp[k]);
            s += sw[k] * (d_y2[row * HID + n] + b2[(size_t)e * HID + n]);
        }
        y[(size_t)t * HID + n] = s;
    }
}

// ---------------- launch ----------------
extern "C" void kernel_launch(void* const* d_in, const int* in_sizes, int n_in,
                              void* d_out, int out_size) {
    const float* x  = (const float*)d_in[0];
    const float* gw = (const float*)d_in[1];
    const float* gb = (const float*)d_in[2];
    const float* w1 = (const float*)d_in[3];
    const float* b1 = (const float*)d_in[4];
    const float* w2 = (const float*)d_in[5];
    const float* b2 = (const float*)d_in[6];
    float* y = (float*)d_out;

    reset_kernel<<<1, 32>>>();
    router_kernel<<<T_TOK, 128>>>(x, gw, gb);
    build_kernel<<<(T_TOK + 255) / 256, 256>>>();

    dim3 g1(INTERN / BN, T_TOK / BM, NE);   // (45, 16, 8)
    gemm1_kernel<<<g1, 256>>>(x, w1, b1);

    dim3 g2(HID / BN, T_TOK / BM, NE);      // (45, 16, 8)
    gemm2_kernel<<<g2, 256>>>(w2);

    combine_kernel<<<T_TOK, 256>>>(b2, y);
}

// round 5
// speedup vs baseline: 5.2324x; 3.4365x over previous
#include <cuda_runtime.h>
#include <cuda_fp16.h>
#include <mma.h>
#include <math.h>
#include <cstdint>

using namespace nvcuda;

#define T_TOK 2048
#define HID   2880
#define INTERN 2880
#define NE    8
#define TOPK  4
#define N1    (2*INTERN)          // 5760
#define ALPHA 1.702f
#define LIMITV 7.0f

// tiling
#define BM 128
#define BN 64
#define BK 32
#define LDA 40                    // BK + 8 halfs pad (80B rows)
#define LDB 72                    // BN + 8 halfs pad (144B rows)
#define LDBF 72                   // epilogue float staging leading dim
#define KT (HID/BK)               // 90

// ---------------- scratch ----------------
__device__ int   d_counts[NE];
__device__ int   d_rtok[NE * T_TOK];
__device__ int   d_pos [T_TOK * TOPK];
__device__ int   d_topidx[T_TOK * TOPK];
__device__ float d_topw [T_TOK * TOPK];

__device__ __half d_xh [(size_t)T_TOK * HID];
__device__ __half d_w1h[(size_t)NE * HID * N1];
__device__ __half d_w2h[(size_t)NE * INTERN * HID];
__device__ __half d_acth[(size_t)NE * T_TOK * INTERN];
__device__ float  d_y2 [(size_t)NE * T_TOK * HID];

__device__ __forceinline__ void cpa16(void* smem, const void* gmem) {
    uint32_t s;
    asm("{ .reg .u64 t; cvta.to.shared.u64 t, %1; cvt.u32.u64 %0, t; }" : "=r"(s) : "l"(smem));
    asm volatile("cp.async.cg.shared.global [%0], [%1], 16;\n" :: "r"(s), "l"(gmem));
}
#define CP_COMMIT() asm volatile("cp.async.commit_group;\n")
#define CP_WAIT1()  asm volatile("cp.async.wait_group 1;\n")

// ---------------- fp32 -> fp16 convert (vectorized) ----------------
__global__ void cvt_half_kernel(const float* __restrict__ in,
                                __half* __restrict__ out, size_t n4) {
    size_t i = (size_t)blockIdx.x * blockDim.x + threadIdx.x;
    if (i >= n4) return;
    float4 v = ((const float4*)in)[i];
    __half2 a = __floats2half2_rn(v.x, v.y);
    __half2 b = __floats2half2_rn(v.z, v.w);
    ((__half2*)out)[i * 2]     = a;
    ((__half2*)out)[i * 2 + 1] = b;
}

// ---------------- router (fp32 exact) ----------------
__global__ void router_kernel(const float* __restrict__ x,
                              const float* __restrict__ gw,
                              const float* __restrict__ gb) {
    int t = blockIdx.x;
    float acc[NE];
    #pragma unroll
    for (int e = 0; e < NE; e++) acc[e] = 0.f;
    for (int h = threadIdx.x; h < HID; h += blockDim.x) {
        float xv = x[(size_t)t * HID + h];
        const float* g = gw + (size_t)h * NE;
        #pragma unroll
        for (int e = 0; e < NE; e++) acc[e] += xv * g[e];
    }
    #pragma unroll
    for (int off = 16; off > 0; off >>= 1)
        #pragma unroll
        for (int e = 0; e < NE; e++)
            acc[e] += __shfl_down_sync(0xffffffffu, acc[e], off);
    __shared__ float sred[4][NE];
    int w = threadIdx.x >> 5, lane = threadIdx.x & 31;
    if (lane == 0)
        #pragma unroll
        for (int e = 0; e < NE; e++) sred[w][e] = acc[e];
    __syncthreads();
    if (threadIdx.x == 0) {
        float lg[NE];
        #pragma unroll
        for (int e = 0; e < NE; e++)
            lg[e] = sred[0][e] + sred[1][e] + sred[2][e] + sred[3][e] + gb[e];
        int idx[TOPK]; float val[TOPK]; bool used[NE];
        #pragma unroll
        for (int e = 0; e < NE; e++) used[e] = false;
        #pragma unroll
        for (int k = 0; k < TOPK; k++) {
            int best = -1; float bv = -INFINITY;
            #pragma unroll
            for (int e = 0; e < NE; e++)
                if (!used[e] && lg[e] > bv) { bv = lg[e]; best = e; }
            used[best] = true; idx[k] = best; val[k] = bv;
        }
        float m = val[0], ex[TOPK], s = 0.f;
        #pragma unroll
        for (int k = 0; k < TOPK; k++) { ex[k] = expf(val[k] - m); s += ex[k]; }
        float inv = 1.f / s;
        #pragma unroll
        for (int k = 0; k < TOPK; k++) {
            d_topidx[t * TOPK + k] = idx[k];
            d_topw [t * TOPK + k] = ex[k] * inv;
        }
    }
}

__global__ void reset_kernel() { if (threadIdx.x < NE) d_counts[threadIdx.x] = 0; }

__global__ void build_kernel() {
    int t = blockIdx.x * blockDim.x + threadIdx.x;
    if (t >= T_TOK) return;
    #pragma unroll
    for (int k = 0; k < TOPK; k++) {
        int e = d_topidx[t * TOPK + k];
        int p = atomicAdd(&d_counts[e], 1);
        d_rtok[e * T_TOK + p] = t;
        d_pos[t * TOPK + k] = p;
    }
}

// ---------------- GEMM1 (fp16 wmma) fused with clamped SwiGLU ----------------
// per CTA: gate tile [BM x BN] and lin tile [BM x BN]; act -> fp16
#define G1_STAGE (BM*LDA + 2*BK*LDB)   // 5120 + 4608 halfs = 9728

__global__ __launch_bounds__(256) void gemm1_kernel(const float* __restrict__ b1) {
    int e  = blockIdx.z;
    int m0 = blockIdx.y * BM;
    int n0 = blockIdx.x * BN;
    int cnt = d_counts[e];
    if (m0 >= cnt) return;

    __shared__ __align__(16) __half sbuf[2 * G1_STAGE];   // 38912 B
    __shared__ int stok[BM];

    int tid = threadIdx.x;
    if (tid < BM) {
        int r = m0 + tid;
        stok[tid] = (r < cnt) ? d_rtok[e * T_TOK + r] : d_rtok[e * T_TOK];
    }
    __syncthreads();

    const __half* Bg = d_w1h + (size_t)e * HID * N1 + n0;
    const __half* Bl = Bg + INTERN;

    auto load_stage = [&](int s, int k0) {
        __half* as = sbuf + s * G1_STAGE;
        __half* bg = as + BM * LDA;
        __half* bl = bg + BK * LDB;
        #pragma unroll
        for (int j = 0; j < 2; j++) {                 // A: 128 rows x 4 chunks
            int idx = tid + j * 256;
            int r = idx >> 2, c = (idx & 3) << 3;
            cpa16(as + r * LDA + c, d_xh + (size_t)stok[r] * HID + k0 + c);
        }
        {                                              // Bg, Bl: 32 rows x 8 chunks
            int r = tid >> 3, c = (tid & 7) << 3;
            const size_t g = (size_t)(k0 + r) * N1 + c;
            cpa16(bg + r * LDB + c, Bg + g);
            cpa16(bl + r * LDB + c, Bl + g);
        }
        CP_COMMIT();
    };

    wmma::fragment<wmma::accumulator, 16, 16, 16, float> ag[2][2], al[2][2];
    #pragma unroll
    for (int i = 0; i < 2; i++)
        #pragma unroll
        for (int j = 0; j < 2; j++) { wmma::fill_fragment(ag[i][j], 0.f); wmma::fill_fragment(al[i][j], 0.f); }

    int wid = tid >> 5, wm = wid >> 1, wn = wid & 1;   // 8 warps: 4m x 2n

    load_stage(0, 0);

    for (int kt = 0; kt < KT; kt++) {
        if (kt + 1 < KT) load_stage((kt + 1) & 1, (kt + 1) * BK);
        else CP_COMMIT();
        CP_WAIT1();
        __syncthreads();
        __half* as = sbuf + (kt & 1) * G1_STAGE;
        __half* bg = as + BM * LDA;
        __half* bl = bg + BK * LDB;
        #pragma unroll
        for (int kk = 0; kk < BK; kk += 16) {
            wmma::fragment<wmma::matrix_a, 16, 16, 16, __half, wmma::row_major> af[2];
            wmma::fragment<wmma::matrix_b, 16, 16, 16, __half, wmma::row_major> bfg[2], bfl[2];
            #pragma unroll
            for (int i = 0; i < 2; i++)
                wmma::load_matrix_sync(af[i], as + (wm * 32 + i * 16) * LDA + kk, LDA);
            #pragma unroll
            for (int j = 0; j < 2; j++) {
                wmma::load_matrix_sync(bfg[j], bg + kk * LDB + wn * 32 + j * 16, LDB);
                wmma::load_matrix_sync(bfl[j], bl + kk * LDB + wn * 32 + j * 16, LDB);
            }
            #pragma unroll
            for (int i = 0; i < 2; i++)
                #pragma unroll
                for (int j = 0; j < 2; j++) {
                    wmma::mma_sync(ag[i][j], af[i], bfg[j], ag[i][j]);
                    wmma::mma_sync(al[i][j], af[i], bfl[j], al[i][j]);
                }
        }
        __syncthreads();
    }

    // ---- fused epilogue: stage gate, stage lin, clamped SwiGLU, fp16 out ----
    float* stg = (float*)sbuf;   // 128*72*4 = 36864 B <= 38912 B
    #pragma unroll
    for (int i = 0; i < 2; i++)
        #pragma unroll
        for (int j = 0; j < 2; j++)
            wmma::store_matrix_sync(stg + (size_t)(wm * 32 + i * 16) * LDBF + wn * 32 + j * 16,
                                    ag[i][j], LDBF, wmma::mem_row_major);
    __syncthreads();

    int r  = tid >> 1;
    int cb = (tid & 1) * 32;
    float gv[32];
    #pragma unroll
    for (int q = 0; q < 8; q++) {
        float4 v = *(const float4*)(stg + r * LDBF + cb + q * 4);
        gv[q*4+0] = v.x; gv[q*4+1] = v.y; gv[q*4+2] = v.z; gv[q*4+3] = v.w;
    }
    __syncthreads();

    #pragma unroll
    for (int i = 0; i < 2; i++)
        #pragma unroll
        for (int j = 0; j < 2; j++)
            wmma::store_matrix_sync(stg + (size_t)(wm * 32 + i * 16) * LDBF + wn * 32 + j * 16,
                                    al[i][j], LDBF, wmma::mem_row_major);
    __syncthreads();

    const float* bgp = b1 + (size_t)e * N1 + n0;
    const float* blp = bgp + INTERN;
    __half* outp = d_acth + (size_t)(e * T_TOK + m0 + r) * INTERN + n0 + cb;
    __half hb[32];
    #pragma unroll
    for (int q = 0; q < 8; q++) {
        float4 lv = *(const float4*)(stg + r * LDBF + cb + q * 4);
        float lraw[4] = {lv.x, lv.y, lv.z, lv.w};
        #pragma unroll
        for (int w = 0; w < 4; w++) {
            int c = cb + q * 4 + w;
            float g = fminf(gv[q*4+w] + bgp[c], LIMITV);
            float l = fminf(fmaxf(lraw[w] + blp[c], -LIMITV), LIMITV);
            float s = 1.0f / (1.0f + expf(-ALPHA * g));
            hb[q*4+w] = __float2half_rn(g * s * (l + 1.0f));
        }
    }
    #pragma unroll
    for (int q = 0; q < 4; q++)
        ((float4*)outp)[q] = ((float4*)hb)[q];
}

// ---------------- GEMM2 (fp16 wmma): y2 = act @ w2[e] ----------------
#define G2_STAGE (BM*LDA + BK*LDB)     // 5120 + 2304 = 7424 halfs

__global__ __launch_bounds__(256) void gemm2_kernel() {
    int e  = blockIdx.z;
    int m0 = blockIdx.y * BM;
    int n0 = blockIdx.x * BN;
    int cnt = d_counts[e];
    if (m0 >= cnt) return;

    __shared__ __align__(16) __half sbuf[2 * G2_STAGE];   // 29696 B

    int tid = threadIdx.x;
    const __half* Abase = d_acth + (size_t)(e * T_TOK + m0) * INTERN;
    const __half* Bbase = d_w2h + (size_t)e * INTERN * HID + n0;

    auto load_stage = [&](int s, int k0) {
        __half* as = sbuf + s * G2_STAGE;
        __half* bs = as + BM * LDA;
        #pragma unroll
        for (int j = 0; j < 2; j++) {
            int idx = tid + j * 256;
            int r = idx >> 2, c = (idx & 3) << 3;
            cpa16(as + r * LDA + c, Abase + (size_t)r * INTERN + k0 + c);
        }
        {
            int r = tid >> 3, c = (tid & 7) << 3;
            cpa16(bs + r * LDB + c, Bbase + (size_t)(k0 + r) * HID + c);
        }
        CP_COMMIT();
    };

    wmma::fragment<wmma::accumulator, 16, 16, 16, float> acc[2][2];
    #pragma unroll
    for (int i = 0; i < 2; i++)
        #pragma unroll
        for (int j = 0; j < 2; j++) wmma::fill_fragment(acc[i][j], 0.f);

    int wid = tid >> 5, wm = wid >> 1, wn = wid & 1;

    load_stage(0, 0);

    for (int kt = 0; kt < KT; kt++) {
        if (kt + 1 < KT) load_stage((kt + 1) & 1, (kt + 1) * BK);
        else CP_COMMIT();
        CP_WAIT1();
        __syncthreads();
        __half* as = sbuf + (kt & 1) * G2_STAGE;
        __half* bs = as + BM * LDA;
        #pragma unroll
        for (int kk = 0; kk < BK; kk += 16) {
            wmma::fragment<wmma::matrix_a, 16, 16, 16, __half, wmma::row_major> af[2];
            wmma::fragment<wmma::matrix_b, 16, 16, 16, __half, wmma::row_major> bf[2];
            #pragma unroll
            for (int i = 0; i < 2; i++)
                wmma::load_matrix_sync(af[i], as + (wm * 32 + i * 16) * LDA + kk, LDA);
            #pragma unroll
            for (int j = 0; j < 2; j++)
                wmma::load_matrix_sync(bf[j], bs + kk * LDB + wn * 32 + j * 16, LDB);
            #pragma unroll
            for (int i = 0; i < 2; i++)
                #pragma unroll
                for (int j = 0; j < 2; j++)
                    wmma::mma_sync(acc[i][j], af[i], bf[j], acc[i][j]);
        }
        __syncthreads();
    }

    float* Cbase = d_y2 + (size_t)(e * T_TOK + m0) * HID + n0;
    #pragma unroll
    for (int i = 0; i < 2; i++)
        #pragma unroll
        for (int j = 0; j < 2; j++)
            wmma::store_matrix_sync(Cbase + (size_t)(wm * 32 + i * 16) * HID + wn * 32 + j * 16,
                                    acc[i][j], HID, wmma::mem_row_major);
}

// ---------------- deterministic combine ----------------
__global__ void combine_kernel(const float* __restrict__ b2,
                               float* __restrict__ y) {
    int t = blockIdx.x;
    __shared__ int se[TOPK]; __shared__ int sp[TOPK]; __shared__ float sw[TOPK];
    if (threadIdx.x < TOPK) {
        se[threadIdx.x] = d_topidx[t * TOPK + threadIdx.x];
        sp[threadIdx.x] = d_pos  [t * TOPK + threadIdx.x];
        sw[threadIdx.x] = d_topw [t * TOPK + threadIdx.x];
    }
    __syncthreads();
    for (int n = threadIdx.x; n < HID; n += blockDim.x) {
        float s = 0.f;
        #pragma unroll
        for (int k = 0; k < TOPK; k++) {
            int e = se[k];
            size_t row = (size_t)(e * T_TOK + sp[k]);
            s += sw[k] * (d_y2[row * HID + n] + b2[(size_t)e * HID + n]);
        }
        y[(size_t)t * HID + n] = s;
    }
}

// ---------------- launch ----------------
extern "C" void kernel_launch(void* const* d_in, const int* in_sizes, int n_in,
                              void* d_out, int out_size) {
    const float* x  = (const float*)d_in[0];
    const float* gw = (const float*)d_in[1];
    const float* gb = (const float*)d_in[2];
    const float* w1 = (const float*)d_in[3];
    const float* b1 = (const float*)d_in[4];
    const float* w2 = (const float*)d_in[5];
    const float* b2 = (const float*)d_in[6];
    float* y = (float*)d_out;

    reset_kernel<<<1, 32>>>();
    router_kernel<<<T_TOK, 128>>>(x, gw, gb);
    build_kernel<<<(T_TOK + 255) / 256, 256>>>();

    // fp32 -> fp16 pre-pass
    {
        __half* p;
        size_t n4;
        cudaGetSymbolAddress((void**)&p, d_xh);
        n4 = (size_t)T_TOK * HID / 4;
        cvt_half_kernel<<<(unsigned)((n4 + 255) / 256), 256>>>(x, p, n4);
        cudaGetSymbolAddress((void**)&p, d_w1h);
        n4 = (size_t)NE * HID * N1 / 4;
        cvt_half_kernel<<<(unsigned)((n4 + 255) / 256), 256>>>(w1, p, n4);
        cudaGetSymbolAddress((void**)&p, d_w2h);
        n4 = (size_t)NE * INTERN * HID / 4;
        cvt_half_kernel<<<(unsigned)((n4 + 255) / 256), 256>>>(w2, p, n4);
    }

    dim3 g1(INTERN / BN, T_TOK / BM, NE);   // (45, 16, 8)
    gemm1_kernel<<<g1, 256>>>(b1);

    dim3 g2(HID / BN, T_TOK / BM, NE);      // (45, 16, 8)
    gemm2_kernel<<<g2, 256>>>();

    combine_kernel<<<T_TOK, 256>>>(b2, y);
}